// round 2
// baseline (speedup 1.0000x reference)
#include <cuda_runtime.h>
#include <cuda_fp16.h>
#include <cstdint>

// QuantLinearMarlin: out[16,8192] = x[16,8192] @ dequant(qweight[1024,8192], scales[64,8192]) + bias
// INT4 symmetric (zero-point 8), group size 128 along K.
// Harness materializes the reference's fp16 tensors as float32 buffers.
//
// Pipeline: (1) convert x fp32->fp16 workspace, (2) HMMA m16n8k16 GEMM with
// in-register INT4 dequant (magic-number LOP3, Sterbenz-exact -8), split-K=8
// into fp32 workspace, (3) reduce + bias epilogue emulating fp16 rounding.

#define MM 16
#define KK 8192
#define NN 8192
#define GROUPSZ 128
#define KSPLIT 8
#define KCHUNK (KK / KSPLIT)                 // 1024
#define GROUPS_PER_CHUNK (KCHUNK / GROUPSZ)  // 8
#define STEPS_PER_GROUP (GROUPSZ / 16)       // 8

// fp32 partial sums: [KSPLIT][M][N] = 4 MB
__device__ float g_ws[KSPLIT * MM * NN];
// x converted to fp16: 256 KB
__device__ __half g_xh[MM * KK];

static __device__ __forceinline__ __half2 u32_as_half2(uint32_t u) {
    return *reinterpret_cast<__half2*>(&u);
}
static __device__ __forceinline__ uint32_t half2_as_u32(__half2 h) {
    return *reinterpret_cast<uint32_t*>(&h);
}

static __device__ __forceinline__ void mma_16816(float c[4],
                                                 uint32_t a0, uint32_t a1, uint32_t a2, uint32_t a3,
                                                 uint32_t b0, uint32_t b1) {
    asm volatile(
        "mma.sync.aligned.m16n8k16.row.col.f32.f16.f16.f32 "
        "{%0,%1,%2,%3}, {%4,%5,%6,%7}, {%8,%9}, {%0,%1,%2,%3};\n"
        : "+f"(c[0]), "+f"(c[1]), "+f"(c[2]), "+f"(c[3])
        : "r"(a0), "r"(a1), "r"(a2), "r"(a3), "r"(b0), "r"(b1));
}

// x fp32 -> fp16. Each thread: 4 floats -> 4 halves. Exact (values are fp16-origin).
__global__ __launch_bounds__(256) void convert_x(const float* __restrict__ x) {
    int i = (blockIdx.x * blockDim.x + threadIdx.x) * 4;
    if (i >= MM * KK) return;
    float4 v = *reinterpret_cast<const float4*>(x + i);
    __half2 lo = __floats2half2_rn(v.x, v.y);
    __half2 hi = __floats2half2_rn(v.z, v.w);
    uint2 p = make_uint2(half2_as_u32(lo), half2_as_u32(hi));
    *reinterpret_cast<uint2*>(g_xh + i) = p;
}

// Main GEMM kernel. Grid: (NN/128, KSPLIT). Block: 128 threads = 4 warps;
// warp w covers 32 cols (4 mma n-blocks). Per warp per k16-step: 4 MMAs.
//
// k-row permutation per 16-k tile (words kb, kb+1; tg = lane&3, tg2=tg>>1, e=tg&1):
//   lane reads word kb+tg2, u = w >> 8e. mma-k rows map to actual k offsets:
//     2tg   -> 8*tg2+2e      2tg+1 -> 8*tg2+2e+4
//     2tg+8 -> 8*tg2+2e+1    2tg+9 -> 8*tg2+2e+5
//   b0 = fp16x2(u nibbles 0,4), b1 = fp16x2(u nibbles 1,5).
//   A fragments follow the same permutation via LDG.128 + 2 PRMT per row.
__global__ __launch_bounds__(128, 4) void qlinear_main(
    const int*   __restrict__ qw,      // [1024][8192] int32 (8 nibbles along K)
    const float* __restrict__ scales)  // [64][8192] f32 (fp16-exact values)
{
    const int tid  = threadIdx.x;
    const int warp = tid >> 5;
    const int lane = tid & 31;
    const int g    = lane >> 2;   // mma group id (A rows g, g+8; B col g)
    const int tg   = lane & 3;
    const int tg2  = tg >> 1;
    const int tge  = tg & 1;

    const int nb     = blockIdx.x * 128 + warp * 32;    // warp col base
    const int kchunk = blockIdx.y * KCHUNK;

    const uint4* pa0 = reinterpret_cast<const uint4*>(g_xh + (size_t)g * KK + kchunk + tg2 * 8);
    const uint4* pa1 = reinterpret_cast<const uint4*>(g_xh + (size_t)(g + 8) * KK + kchunk + tg2 * 8);
    const int* pb = qw + ((size_t)(kchunk >> 3) + tg2) * NN + nb + g;
    const float* psc = scales + (size_t)(kchunk / GROUPSZ) * NN + nb + g;

    float c[4][4];
    #pragma unroll
    for (int j = 0; j < 4; ++j)
        #pragma unroll
        for (int i = 0; i < 4; ++i) c[j][i] = 0.0f;

    const __half2 h1032 = u32_as_half2(0x64086408u);  // (1032, 1032)

    for (int grp = 0; grp < GROUPS_PER_CHUNK; ++grp) {
        __half2 s2[4];
        #pragma unroll
        for (int j = 0; j < 4; ++j) {
            __half s = __float2half_rn(psc[8 * j]);    // exact (fp16-origin)
            s2[j] = __half2half2(s);
        }
        psc += NN;

        #pragma unroll
        for (int it = 0; it < STEPS_PER_GROUP; ++it) {
            // ---- A fragments ----
            uint4 va = pa0[0];
            uint4 vb = pa1[0];
            pa0 += 2; pa1 += 2;
            uint32_t xa = tge ? va.y : va.x;   // halves (2e, 2e+1)
            uint32_t xb = tge ? va.w : va.z;   // halves (2e+4, 2e+5)
            uint32_t ya = tge ? vb.y : vb.x;
            uint32_t yb = tge ? vb.w : vb.z;
            uint32_t a0 = __byte_perm(xa, xb, 0x5410);  // (h[2e],   h[2e+4]) row g
            uint32_t a1 = __byte_perm(ya, yb, 0x5410);  // row g+8
            uint32_t a2 = __byte_perm(xa, xb, 0x7632);  // (h[2e+1], h[2e+5]) row g
            uint32_t a3 = __byte_perm(ya, yb, 0x7632);  // row g+8

            // ---- B fragments: dequant 4 column-blocks ----
            #pragma unroll
            for (int j = 0; j < 4; ++j) {
                uint32_t w = (uint32_t)pb[8 * j];
                uint32_t u = w >> (tge * 8);
                uint32_t q0 = (u & 0x000F000Fu) | 0x64006400u;         // 1024+v
                uint32_t q1 = ((u >> 4) & 0x000F000Fu) | 0x64006400u;
                // exact: (1024+v) - 1032 = v-8 (Sterbenz), then * scale (single RN)
                __half2 b0 = __hmul2(__hsub2(u32_as_half2(q0), h1032), s2[j]);
                __half2 b1 = __hmul2(__hsub2(u32_as_half2(q1), h1032), s2[j]);
                mma_16816(c[j], a0, a1, a2, a3, half2_as_u32(b0), half2_as_u32(b1));
            }
            pb += 2 * NN;
        }
    }

    // ---- store fp32 partials (full overwrite of this split slice) ----
    float* wsp = g_ws + (size_t)blockIdx.y * MM * NN;
    #pragma unroll
    for (int j = 0; j < 4; ++j) {
        int col = nb + 8 * j + 2 * tg;
        *reinterpret_cast<float2*>(wsp + (size_t)g * NN + col)       = make_float2(c[j][0], c[j][1]);
        *reinterpret_cast<float2*>(wsp + (size_t)(g + 8) * NN + col) = make_float2(c[j][2], c[j][3]);
    }
}

// Reduce KSPLIT partials, emulate fp16 rounding of dot result, add fp16 bias,
// round to fp16, emit as f32. One thread per 2 output cols.
__global__ __launch_bounds__(256) void qlinear_epilogue(
    const float* __restrict__ bias, float* __restrict__ out)
{
    int idx = blockIdx.x * blockDim.x + threadIdx.x;
    int idx2 = idx * 2;
    if (idx2 >= MM * NN) return;
    int m = idx2 / NN;
    int n = idx2 - m * NN;

    float ax = 0.0f, ay = 0.0f;
    #pragma unroll
    for (int s = 0; s < KSPLIT; ++s) {
        float2 v = *reinterpret_cast<const float2*>(g_ws + ((size_t)s * MM + m) * NN + n);
        ax += v.x; ay += v.y;
    }
    float bx = bias[n], by = bias[n + 1];
    // fp16 semantics: h = f16(dot); out = f16(h + b)
    float hx = __half2float(__float2half_rn(ax));
    float hy = __half2float(__float2half_rn(ay));
    float ox = __half2float(__float2half_rn(hx + bx));
    float oy = __half2float(__float2half_rn(hy + by));
    *reinterpret_cast<float2*>(out + idx2) = make_float2(ox, oy);
}

extern "C" void kernel_launch(void* const* d_in, const int* in_sizes, int n_in,
                              void* d_out, int out_size) {
    const float* x      = (const float*)d_in[0];
    const int*   qw     = (const int*)d_in[1];
    const float* scales = (const float*)d_in[2];
    const float* bias   = (const float*)d_in[3];
    float* out = (float*)d_out;

    convert_x<<<(MM * KK / 4 + 255) / 256, 256>>>(x);

    dim3 grid1(NN / 128, KSPLIT);
    qlinear_main<<<grid1, 128>>>(qw, scales);

    int total = (MM * NN) / 2;
    qlinear_epilogue<<<(total + 255) / 256, 256>>>(bias, out);
}